// round 1
// baseline (speedup 1.0000x reference)
#include <cuda_runtime.h>
#include <math.h>

#define BATCH 4
#define CH    128
#define NTOK  4096   // 64*64
#define TQ    64
#define TK    64
#define QTILES (NTOK / TQ)           // 64
#define NBLK   (BATCH * QTILES)      // 256

// Scratch for Q, K, V in token-major layout [b][n][c] (contiguous rows of 128 floats).
__device__ float g_Q[BATCH * NTOK * CH];
__device__ float g_K[BATCH * NTOK * CH];
__device__ float g_V[BATCH * NTOK * CH];

// ---------------------------------------------------------------------------
// Kernel 1: QKV projections. y[t,co] = sum_c in[t,c] * W[co,c] + bias[co]
// blockIdx.y selects which projection (0=Q from prompt, 1=K from x, 2=V from x).
// Block handles 64 tokens x 128 outputs, 256 threads, 4x8 register microtile.
// ---------------------------------------------------------------------------
__global__ __launch_bounds__(256, 1)
void qkv_kernel(const float* __restrict__ prompt, const float* __restrict__ x,
                const float* __restrict__ Wq, const float* __restrict__ bq,
                const float* __restrict__ Wk, const float* __restrict__ bk,
                const float* __restrict__ Wv, const float* __restrict__ bv)
{
    extern __shared__ float sm[];
    float* Xs = sm;             // 64 x 132 (token-major input tile, padded)
    float* Wt = sm + 64 * 132;  // 128 x 132 (W transposed: Wt[c][co])

    const int which = blockIdx.y;
    const float* in   = (which == 0) ? prompt : x;
    const float* W    = (which == 0) ? Wq : (which == 1) ? Wk : Wv;
    const float* bias = (which == 0) ? bq : (which == 1) ? bk : bv;
    float* outg       = (which == 0) ? g_Q : (which == 1) ? g_K : g_V;

    const int b  = blockIdx.x >> 6;         // blockIdx.x / 64
    const int nb = (blockIdx.x & 63) * 64;  // token tile base
    const int tid = threadIdx.x;

    // Load input tile, transposing (b,c,n) -> Xs[t][c]. Coalesced on n.
    for (int idx = tid; idx < 64 * CH; idx += 256) {
        int t = idx & 63, c = idx >> 6;
        Xs[t * 132 + c] = in[((size_t)b * CH + c) * NTOK + nb + t];
    }
    // Load W transposed: Wt[c][co] = W[co][c]. Coalesced on c.
    for (int idx = tid; idx < CH * CH; idx += 256) {
        int c = idx & 127, co = idx >> 7;
        Wt[c * 132 + co] = W[co * CH + c];
    }
    __syncthreads();

    const int tx = tid & 15, ty = tid >> 4;
    float4 ba = *(const float4*)&bias[tx * 4];
    float4 bb = *(const float4*)&bias[64 + tx * 4];
    float acc[4][8];
    #pragma unroll
    for (int i = 0; i < 4; i++) {
        acc[i][0] = ba.x; acc[i][1] = ba.y; acc[i][2] = ba.z; acc[i][3] = ba.w;
        acc[i][4] = bb.x; acc[i][5] = bb.y; acc[i][6] = bb.z; acc[i][7] = bb.w;
    }

    #pragma unroll 4
    for (int c = 0; c < CH; c++) {
        float4 wa = *(float4*)&Wt[c * 132 + tx * 4];
        float4 wb = *(float4*)&Wt[c * 132 + 64 + tx * 4];
        #pragma unroll
        for (int i = 0; i < 4; i++) {
            float xv = Xs[(ty * 4 + i) * 132 + c];
            acc[i][0] += xv * wa.x; acc[i][1] += xv * wa.y;
            acc[i][2] += xv * wa.z; acc[i][3] += xv * wa.w;
            acc[i][4] += xv * wb.x; acc[i][5] += xv * wb.y;
            acc[i][6] += xv * wb.z; acc[i][7] += xv * wb.w;
        }
    }

    #pragma unroll
    for (int i = 0; i < 4; i++) {
        int n = nb + ty * 4 + i;
        float* orow = &outg[(size_t)(b * NTOK + n) * CH];
        *(float4*)&orow[tx * 4]      = make_float4(acc[i][0], acc[i][1], acc[i][2], acc[i][3]);
        *(float4*)&orow[64 + tx * 4] = make_float4(acc[i][4], acc[i][5], acc[i][6], acc[i][7]);
    }
}

// ---------------------------------------------------------------------------
// Kernel 2: fused masked flash-attention + residual + LayerNorm.
// One block = 64 query tokens of one batch. Online softmax over 64 key tiles.
// 256 threads as 16x16. Score stage: 4 rows x 4 cols (cols m = tx + 16j).
// Output stage: 4 rows x 8 channels (cols co = tx*4+j and 64+tx*4+j).
// ---------------------------------------------------------------------------
__global__ __launch_bounds__(256, 1)
void attn_kernel(const float* __restrict__ x, const int* __restrict__ mask,
                 const float* __restrict__ gamma, const float* __restrict__ beta,
                 float* __restrict__ out)
{
    extern __shared__ float sm[];
    float* Qs   = sm;               // 64 x 132
    float* Ks   = Qs + 64 * 132;    // 64 x 132
    float* Vs   = Ks + 64 * 132;    // 64 x 132
    float* Ss   = Vs + 64 * 132;    // 64 x 66 (probabilities)
    float* m_s  = Ss + 64 * 66;     // 64 running max
    float* l_s  = m_s + 64;         // 64 running sum
    float* sc_s = l_s + 64;         // 64 rescale factors
    float* mk_s = sc_s + 64;        // 64 additive mask for current key tile

    const int b  = blockIdx.x >> 6;
    const int qb = (blockIdx.x & 63) * 64;
    const int tid = threadIdx.x;
    const int tx = tid & 15, ty = tid >> 4;
    const float qscale = 0.0883883476483184f; // 1/sqrt(128)

    // Load Q tile, pre-scaled by 1/sqrt(C).
    const float4* Qrow = (const float4*)&g_Q[(size_t)(b * NTOK + qb) * CH];
    for (int idx = tid; idx < 64 * 32; idx += 256) {
        int t = idx >> 5, c4 = idx & 31;
        float4 v = Qrow[t * 32 + c4];
        v.x *= qscale; v.y *= qscale; v.z *= qscale; v.w *= qscale;
        *(float4*)&Qs[t * 132 + c4 * 4] = v;
    }
    if (tid < 64) { m_s[tid] = -INFINITY; l_s[tid] = 0.f; }

    float o[4][8];
    #pragma unroll
    for (int i = 0; i < 4; i++)
        #pragma unroll
        for (int j = 0; j < 8; j++) o[i][j] = 0.f;

    for (int kt = 0; kt < NTOK / TK; kt++) {
        __syncthreads();  // previous O-stage done reading Vs/Ss
        const int kb = kt * 64;
        const float4* Kr = (const float4*)&g_K[(size_t)(b * NTOK + kb) * CH];
        const float4* Vr = (const float4*)&g_V[(size_t)(b * NTOK + kb) * CH];
        for (int idx = tid; idx < 64 * 32; idx += 256) {
            int t = idx >> 5, c4 = idx & 31;
            *(float4*)&Ks[t * 132 + c4 * 4] = Kr[t * 32 + c4];
            *(float4*)&Vs[t * 132 + c4 * 4] = Vr[t * 32 + c4];
        }
        if (tid < 64)
            mk_s[tid] = (mask[b * NTOK + kb + tid] > 0) ? 0.f : -1e30f;
        __syncthreads();

        // --- scores S = Q K^T (rows ty*4+i, cols tx+16j) ---
        float s[4][4];
        #pragma unroll
        for (int i = 0; i < 4; i++)
            #pragma unroll
            for (int j = 0; j < 4; j++) s[i][j] = 0.f;

        #pragma unroll 2
        for (int c4 = 0; c4 < 32; c4++) {
            float4 q[4], k[4];
            #pragma unroll
            for (int i = 0; i < 4; i++)
                q[i] = *(float4*)&Qs[(ty * 4 + i) * 132 + c4 * 4];
            #pragma unroll
            for (int j = 0; j < 4; j++)
                k[j] = *(float4*)&Ks[(tx + j * 16) * 132 + c4 * 4];
            #pragma unroll
            for (int i = 0; i < 4; i++)
                #pragma unroll
                for (int j = 0; j < 4; j++)
                    s[i][j] += q[i].x * k[j].x + q[i].y * k[j].y
                             + q[i].z * k[j].z + q[i].w * k[j].w;
        }
        #pragma unroll
        for (int j = 0; j < 4; j++) {
            float ma = mk_s[tx + j * 16];
            #pragma unroll
            for (int i = 0; i < 4; i++) s[i][j] += ma;
        }

        // --- online softmax update, row-owned by a 16-lane group ---
        #pragma unroll
        for (int i = 0; i < 4; i++) {
            int r = ty * 4 + i;
            float tm = fmaxf(fmaxf(s[i][0], s[i][1]), fmaxf(s[i][2], s[i][3]));
            #pragma unroll
            for (int off = 8; off >= 1; off >>= 1)
                tm = fmaxf(tm, __shfl_xor_sync(0xffffffffu, tm, off, 16));
            float mold = m_s[r];
            float mnew = fmaxf(mold, tm);
            float rs = 0.f;
            #pragma unroll
            for (int j = 0; j < 4; j++) {
                float p = __expf(s[i][j] - mnew);
                s[i][j] = p; rs += p;
            }
            #pragma unroll
            for (int off = 8; off >= 1; off >>= 1)
                rs += __shfl_xor_sync(0xffffffffu, rs, off, 16);
            if (tx == 0) {
                float scl = __expf(mold - mnew);
                sc_s[r] = scl;
                l_s[r]  = l_s[r] * scl + rs;
                m_s[r]  = mnew;
            }
            #pragma unroll
            for (int j = 0; j < 4; j++)
                Ss[r * 66 + tx + j * 16] = s[i][j];
        }
        __syncthreads();

        // --- rescale accumulator, then O += P @ V ---
        #pragma unroll
        for (int i = 0; i < 4; i++) {
            float f = sc_s[ty * 4 + i];
            #pragma unroll
            for (int j = 0; j < 8; j++) o[i][j] *= f;
        }
        #pragma unroll 2
        for (int k = 0; k < 64; k++) {
            float4 va = *(float4*)&Vs[k * 132 + tx * 4];
            float4 vb = *(float4*)&Vs[k * 132 + 64 + tx * 4];
            #pragma unroll
            for (int i = 0; i < 4; i++) {
                float p = Ss[(ty * 4 + i) * 66 + k];
                o[i][0] += p * va.x; o[i][1] += p * va.y;
                o[i][2] += p * va.z; o[i][3] += p * va.w;
                o[i][4] += p * vb.x; o[i][5] += p * vb.y;
                o[i][6] += p * vb.z; o[i][7] += p * vb.w;
            }
        }
    }
    __syncthreads();  // final l_s visible to all lanes

    // --- epilogue: normalize, residual, LayerNorm over channels, write out ---
    float g[8], be[8];
    #pragma unroll
    for (int j = 0; j < 8; j++) {
        int co = (j < 4) ? tx * 4 + j : 64 + tx * 4 + (j - 4);
        g[j] = gamma[co]; be[j] = beta[co];
    }
    #pragma unroll
    for (int i = 0; i < 4; i++) {
        int r = ty * 4 + i;
        int n = qb + r;
        float invl = 1.f / l_s[r];
        float v[8], sum = 0.f, sq = 0.f;
        #pragma unroll
        for (int j = 0; j < 8; j++) {
            int co = (j < 4) ? tx * 4 + j : 64 + tx * 4 + (j - 4);
            float val = o[i][j] * invl + x[((size_t)b * CH + co) * NTOK + n];
            v[j] = val; sum += val; sq += val * val;
        }
        #pragma unroll
        for (int off = 8; off >= 1; off >>= 1) {
            sum += __shfl_xor_sync(0xffffffffu, sum, off, 16);
            sq  += __shfl_xor_sync(0xffffffffu, sq,  off, 16);
        }
        float mu   = sum * (1.f / 128.f);
        float var  = sq  * (1.f / 128.f) - mu * mu;
        float rstd = rsqrtf(var + 1e-5f);
        #pragma unroll
        for (int j = 0; j < 8; j++) {
            int co = (j < 4) ? tx * 4 + j : 64 + tx * 4 + (j - 4);
            out[((size_t)b * CH + co) * NTOK + n] = (v[j] - mu) * rstd * g[j] + be[j];
        }
    }
}

// ---------------------------------------------------------------------------
extern "C" void kernel_launch(void* const* d_in, const int* in_sizes, int n_in,
                              void* d_out, int out_size)
{
    const float* prompt = (const float*)d_in[0];
    const float* x      = (const float*)d_in[1];
    const float* Wq     = (const float*)d_in[2];
    const float* bq     = (const float*)d_in[3];
    const float* Wk     = (const float*)d_in[4];
    const float* bk     = (const float*)d_in[5];
    const float* Wv     = (const float*)d_in[6];
    const float* bv     = (const float*)d_in[7];
    const float* gamma  = (const float*)d_in[8];
    const float* beta   = (const float*)d_in[9];
    const int*   mask   = (const int*)d_in[10];
    float* out = (float*)d_out;

    const int qkv_smem  = (64 * 132 + 128 * 132) * (int)sizeof(float);   // 101376
    const int attn_smem = (3 * 64 * 132 + 64 * 66 + 4 * 64) * (int)sizeof(float); // 119296

    // Idempotent attribute sets (no static guards; safe during graph capture).
    cudaFuncSetAttribute(qkv_kernel,  cudaFuncAttributeMaxDynamicSharedMemorySize, qkv_smem);
    cudaFuncSetAttribute(attn_kernel, cudaFuncAttributeMaxDynamicSharedMemorySize, attn_smem);

    dim3 grid_qkv(NBLK, 3);
    qkv_kernel<<<grid_qkv, 256, qkv_smem>>>(prompt, x, Wq, bq, Wk, bk, Wv, bv);
    attn_kernel<<<NBLK, 256, attn_smem>>>(x, mask, gamma, beta, out);
}